// round 16
// baseline (speedup 1.0000x reference)
#include <cuda_runtime.h>
#include <cuda_fp16.h>
#include <cstdint>
#include <math.h>

// Problem constants (MoDRouter_48387101556956: fixed shapes)
#define BB   4
#define NN   4096
#define DD   1024
#define DFFN 4096
#define KK   2048
#define MM   (BB * KK)   // 8192 selected tokens total

// GEMM2 uniform split-K: 512 tiles x 4 K-quarters -> 2048 CTAs of 16 K-iters
// (same grid shape as GEMM1, which packs at ~99% on 296 slots)
#define N_TILES2   512
#define NQ         4

// ---------------------------------------------------------------------------
// Device scratch
// ---------------------------------------------------------------------------
__device__ float  g_scores[BB * NN];
__device__ int    g_sel[MM];                       // selected token idx per (b,j)
__device__ int    g_unsel[MM];                     // complement token idx per (b,j)
__device__ __half g_a[(size_t)MM * DD];            // gathered fp16 A (16 MB)
__device__ __half g_w1t[(size_t)DFFN * DD];        // w1^T (n-major, K contig), fp16
__device__ __half g_w2t[(size_t)DD * DFFN];        // w2^T (n-major, K contig), fp16
__device__ __half g_h[(size_t)MM * DFFN];          // gelu(x@w1+b1), fp16 (64 MB)
__device__ float  g_part[(size_t)N_TILES2 * NQ * 128 * 128];  // fp32 partials (128 MB)
__device__ int    g_cnt[N_TILES2];                 // split-K arrival tickets

// ---------------------------------------------------------------------------
// Helpers
// ---------------------------------------------------------------------------
__device__ __forceinline__ uint32_t smem_u32(const void* p) {
    uint32_t a;
    asm("{ .reg .u64 t; cvta.to.shared.u64 t, %1; cvt.u32.u64 %0, t; }" : "=r"(a) : "l"(p));
    return a;
}
// gelu-tanh with HW MUFU tanh (sm_75+): |err| <= ~2^-11, inside error budget
__device__ __forceinline__ float gelu_fast(float u) {
    float arg = 0.7978845608028654f * (u + 0.044715f * u * u * u);
    float t;
    asm("tanh.approx.f32 %0, %1;" : "=f"(t) : "f"(arg));
    return 0.5f * u * (1.0f + t);
}

#define CP_ASYNC16(dst, src) \
    asm volatile("cp.async.cg.shared.global [%0], [%1], 16;" :: "r"(dst), "l"(src) : "memory")
#define CP_COMMIT() asm volatile("cp.async.commit_group;" ::: "memory")
#define CP_WAIT1()  asm volatile("cp.async.wait_group 1;" ::: "memory")

// m16n8k16 row.col fp16 MMA, fp32 accumulate (base-ISA, legal on sm_103)
#define MMA_F16(c, a, b0, b1)                                                         \
    asm volatile("mma.sync.aligned.m16n8k16.row.col.f32.f16.f16.f32 "                 \
                 "{%0,%1,%2,%3}, {%4,%5,%6,%7}, {%8,%9}, {%0,%1,%2,%3};"              \
                 : "+f"((c)[0]), "+f"((c)[1]), "+f"((c)[2]), "+f"((c)[3])             \
                 : "r"((a)[0]), "r"((a)[1]), "r"((a)[2]), "r"((a)[3]), "r"(b0), "r"(b1))

// ldmatrix 4x m8n8 b16 (non-transposed)
#define LDSM_X4(r0, r1, r2, r3, addr)                                                 \
    asm volatile("ldmatrix.sync.aligned.m8n8.x4.shared.b16 {%0,%1,%2,%3}, [%4];"      \
                 : "=r"(r0), "=r"(r1), "=r"(r2), "=r"(r3) : "r"(addr))

// ---------------------------------------------------------------------------
// 1) Gate scores — one warp per row. Zeroes ALL split-K tickets each launch.
// ---------------------------------------------------------------------------
__global__ void scores_kernel(const float* __restrict__ x,
                              const float* __restrict__ gw) {
    if (blockIdx.x == 0)
        for (int i = threadIdx.x; i < N_TILES2; i += blockDim.x) g_cnt[i] = 0;
    int gwarp = (blockIdx.x * blockDim.x + threadIdx.x) >> 5;
    int lane  = threadIdx.x & 31;
    if (gwarp >= BB * NN) return;
    const float4* xr = reinterpret_cast<const float4*>(x + (size_t)gwarp * DD);
    const float4* g4 = reinterpret_cast<const float4*>(gw);
    float s = 0.0f;
#pragma unroll
    for (int i = 0; i < DD / 4 / 32; ++i) {
        float4 a = xr[lane + i * 32];
        float4 b = g4[lane + i * 32];
        s += a.x * b.x + a.y * b.y + a.z * b.z + a.w * b.w;
    }
#pragma unroll
    for (int o = 16; o; o >>= 1) s += __shfl_xor_sync(0xFFFFFFFFu, s, o);
    if (lane == 0) g_scores[gwarp] = s;
}

// ---------------------------------------------------------------------------
// 2) MID kernel: CTAs 0-3 run per-batch exact top-K (radix select) AND build
//    the complement list; CTAs 4..2051 transpose w1/w2 to fp16 K-major.
// ---------------------------------------------------------------------------
#define MID_SMEM 33824   // keys 16K | eqidx/flags 16K | hist 1K | ctrl 32B

__global__ void mid_kernel(const float* __restrict__ w1,
                           const float* __restrict__ w2) {
    extern __shared__ char sh[];
    int bid = blockIdx.x, tid = threadIdx.x, nthr = blockDim.x;

    if (bid >= 4) {
        // ---- transpose path: 4 subtiles of 32x32 per CTA ----
        float (*t)[32][33] = reinterpret_cast<float (*)[32][33]>(sh);
        int sub  = tid >> 8;
        int stid = tid & 255;
        int tx = stid & 31, ty = stid >> 5;
        const float* src; __half* dst; int R, C, bx, by;
        if (bid < 4 + 1024) {
            int r = (bid - 4) * 4 + sub;
            src = w1; dst = g_w1t; R = DD; C = DFFN;
            bx = (r & 127) * 32; by = (r >> 7) * 32;
        } else {
            int r = (bid - 4 - 1024) * 4 + sub;
            src = w2; dst = g_w2t; R = DFFN; C = DD;
            bx = (r & 31) * 32; by = (r >> 5) * 32;
        }
#pragma unroll
        for (int i = 0; i < 32; i += 8)
            t[sub][ty + i][tx] = src[(size_t)(by + ty + i) * C + bx + tx];
        __syncthreads();
#pragma unroll
        for (int i = 0; i < 32; i += 8)
            dst[(size_t)(bx + ty + i) * R + by + tx] = __float2half_rn(t[sub][tx][ty + i]);
        return;
    }

    // ---- top-K path (CTAs 0-3, one batch each) ----
    uint32_t* keys  = reinterpret_cast<uint32_t*>(sh);
    int*      eqidx = reinterpret_cast<int*>(sh + 16384);
    int*      hist  = reinterpret_cast<int*>(sh + 32768);
    int*      ctrl  = reinterpret_cast<int*>(sh + 33792);
    int b = bid;

    for (int i = tid; i < NN; i += nthr) {
        uint32_t u = __float_as_uint(g_scores[b * NN + i]);
        u = (u & 0x80000000u) ? ~u : (u | 0x80000000u);   // monotone map
        keys[i] = u;
    }
    if (tid == 0) { ctrl[1] = KK; ctrl[2] = 0; ctrl[4] = 0; }
    __syncthreads();

    for (int byte = 3; byte >= 0; --byte) {
        if (tid < 256) hist[tid] = 0;
        __syncthreads();
        int shift = byte * 8;
        uint32_t pfx = (uint32_t)ctrl[4];
        for (int i = tid; i < NN; i += nthr) {
            uint32_t u = keys[i];
            bool active = (byte == 3) || ((u >> (shift + 8)) == pfx);
            if (active) atomicAdd(&hist[(u >> shift) & 0xFF], 1);
        }
        __syncthreads();
        if (tid == 0) {
            int R = ctrl[1], cum = 0, v = 255;
            for (; v > 0; --v) {
                if (cum + hist[v] >= R) break;
                cum += hist[v];
            }
            ctrl[0] = v;
            ctrl[1] = R - cum;
            ctrl[4] = (int)((pfx << 8) | (uint32_t)v);
        }
        __syncthreads();
        int bnd = ctrl[0];
        for (int i = tid; i < NN; i += nthr) {
            uint32_t u = keys[i];
            bool active = (byte == 3) || ((u >> (shift + 8)) == pfx);
            if (active && (int)((u >> shift) & 0xFF) > bnd) {
                int slot = atomicAdd(&ctrl[2], 1);
                g_sel[b * KK + slot] = i;
            }
        }
        __syncthreads();
    }

    // Exact tie handling at the threshold key: smallest indices win (jax rule)
    if (tid == 0) ctrl[3] = 0;
    __syncthreads();
    uint32_t T = (uint32_t)ctrl[4];
    for (int i = tid; i < NN; i += nthr)
        if (keys[i] == T) eqidx[atomicAdd(&ctrl[3], 1)] = i;
    __syncthreads();
    int R = ctrl[1], en = ctrl[3];
    for (int j = tid; j < en; j += nthr) {
        int idx = eqidx[j], rank = 0;
        for (int t2 = 0; t2 < en; ++t2) rank += (eqidx[t2] < idx);
        if (rank < R) {
            int slot = atomicAdd(&ctrl[2], 1);
            g_sel[b * KK + slot] = idx;
        }
    }

    // ---- complement list: flags from g_sel (just written by THIS CTA) ----
    __syncthreads();
    int* flags = eqidx;                         // reuse 16KB as 4096 int flags
    for (int i = tid; i < NN; i += nthr) flags[i] = 0;
    if (tid == 0) ctrl[5] = 0;
    __syncthreads();
    for (int j = tid; j < KK; j += nthr) flags[g_sel[b * KK + j]] = 1;
    __syncthreads();
    for (int i = tid; i < NN; i += nthr)
        if (!flags[i]) {
            int slot = atomicAdd(&ctrl[5], 1);
            g_unsel[b * KK + slot] = i;
        }
}

// ---------------------------------------------------------------------------
// 3) Gather selected rows -> fp16 g_a  ||  copy non-selected rows x -> out
// ---------------------------------------------------------------------------
__global__ void gather_copy_kernel(const float* __restrict__ x,
                                   float* __restrict__ out) {
    int bid = blockIdx.x, c = threadIdx.x;
    if (bid < MM) {
        int tok = g_sel[bid];
        size_t src = ((size_t)(bid >> 11) * NN + tok) * DD + c * 4;
        float4 v = *reinterpret_cast<const float4*>(x + src);
        __half2 h0 = __floats2half2_rn(v.x, v.y);
        __half2 h1 = __floats2half2_rn(v.z, v.w);
        uint2 pk;
        pk.x = *reinterpret_cast<uint32_t*>(&h0);
        pk.y = *reinterpret_cast<uint32_t*>(&h1);
        *reinterpret_cast<uint2*>(g_a + (size_t)bid * DD + c * 4) = pk;
    } else {
        int m2 = bid - MM;
        int tok = g_unsel[m2];
        size_t base = ((size_t)(m2 >> 11) * NN + tok) * DD + c * 4;
        *reinterpret_cast<float4*>(out + base) =
            *reinterpret_cast<const float4*>(x + base);
    }
}

// ---------------------------------------------------------------------------
// fp16 mma.sync GEMM core (mainloop at the legacy-HMMA rate floor):
// CTA tile 128x128, 256 thr (8 warps 4Mx2N, warp 32x64), lb(256,2) -> 2/SM.
//   MODE 0: ffn1, 2D grid (32,64), K=1024:  g_h = h(gelu(g_a @ w1t^T + b1))
//   MODE 1: ffn2, 1D grid 2048, uniform 4-way split-K (16 iters each):
//     every quarter writes an fp32 partial; the 4th arriver combines all
//     four (+bias+residual) and scatters into out.
// ---------------------------------------------------------------------------
#define HPITCH_B 144                               // bytes per row (72 halves)
#define A_STG (128 * HPITCH_B)
#define B_STG (128 * HPITCH_B)
#define NSTG 3
#define GSMEM_SZ (NSTG * (A_STG + B_STG))          // 110592 B per CTA

__device__ __forceinline__ void ld_stage(uint32_t sb, int stage,
                                         const __half* __restrict__ A,
                                         const __half* __restrict__ Bw,
                                         int Kdim, int mt, int nt, int k0, int tid) {
    uint32_t abase = sb + stage * A_STG;
    uint32_t bbase = sb + NSTG * A_STG + stage * B_STG;
#pragma unroll
    for (int i = 0; i < 4; ++i) {
        int lin = i * 256 + tid;
        int row = lin >> 3, ch = lin & 7;
        CP_ASYNC16(abase + row * HPITCH_B + ch * 16,
                   A + (size_t)(mt * 128 + row) * Kdim + k0 + ch * 8);
    }
#pragma unroll
    for (int i = 0; i < 4; ++i) {
        int lin = i * 256 + tid;
        int row = lin >> 3, ch = lin & 7;
        CP_ASYNC16(bbase + row * HPITCH_B + ch * 16,
                   Bw + (size_t)(nt * 128 + row) * Kdim + k0 + ch * 8);
    }
}

template <int MODE>
__global__ __launch_bounds__(256, 2)
void mma_gemm(const float* __restrict__ bias,
              const float* __restrict__ xin,
              float* __restrict__ outp) {
    extern __shared__ uint32_t smw[];
    __shared__ int sh_ticket;
    const __half* A    = (MODE == 0) ? g_a   : g_h;
    const __half* Bw   = (MODE == 0) ? g_w1t : g_w2t;
    const int     Kdim = (MODE == 0) ? DD : DFFN;

    int tid = threadIdx.x, lane = tid & 31, wid = tid >> 5;
    int wm = wid >> 1, wn = wid & 1;               // warp tile: rows wm*32, cols wn*64

    // tile decode
    int mt, nt, k0base, KT, tile = 0;
    if (MODE == 0) {
        mt = blockIdx.y; nt = blockIdx.x; k0base = 0; KT = Kdim / 64;
    } else {
        int bid = blockIdx.x;
        tile = bid >> 2;                           // 0..511
        int q = bid & 3;
        k0base = q * 1024; KT = 16;
        mt = tile >> 3; nt = tile & 7;
    }
    uint32_t sb = smem_u32(smw);

    int lrow = ((lane >> 3) & 1) * 8 + (lane & 7);
    int koff = (lane >= 16) ? 16 : 0;
    uint32_t a_off[2], b_off[4];
#pragma unroll
    for (int mi = 0; mi < 2; ++mi)
        a_off[mi] = (wm * 32 + mi * 16 + lrow) * HPITCH_B + koff;
#pragma unroll
    for (int p = 0; p < 4; ++p)
        b_off[p] = (wn * 64 + p * 16 + lrow) * HPITCH_B + koff;

    float acc[2][8][4];
#pragma unroll
    for (int mi = 0; mi < 2; ++mi)
#pragma unroll
        for (int ni = 0; ni < 8; ++ni)
#pragma unroll
            for (int q = 0; q < 4; ++q) acc[mi][ni][q] = 0.0f;

    ld_stage(sb, 0, A, Bw, Kdim, mt, nt, k0base, tid);
    CP_COMMIT();
    ld_stage(sb, 1, A, Bw, Kdim, mt, nt, k0base + 64, tid);
    CP_COMMIT();

    int stage = 0;
    for (int k = 0; k < KT; ++k) {
        CP_WAIT1();
        __syncthreads();

        int pstage = stage + 2 >= NSTG ? stage + 2 - NSTG : stage + 2;
        if (k + 2 < KT)
            ld_stage(sb, pstage, A, Bw, Kdim, mt, nt, k0base + (k + 2) * 64, tid);
        CP_COMMIT();

        uint32_t As_addr = sb + stage * A_STG;
        uint32_t Bs_addr = sb + NSTG * A_STG + stage * B_STG;
#pragma unroll
        for (int ks = 0; ks < 4; ++ks) {           // 4 x K=16
            uint32_t a[2][4];
#pragma unroll
            for (int mi = 0; mi < 2; ++mi)
                LDSM_X4(a[mi][0], a[mi][1], a[mi][2], a[mi][3],
                        As_addr + a_off[mi] + ks * 32);
#pragma unroll
            for (int p = 0; p < 4; ++p) {
                uint32_t b0, b1, b2, b3;
                LDSM_X4(b0, b1, b2, b3, Bs_addr + b_off[p] + ks * 32);
#pragma unroll
                for (int mi = 0; mi < 2; ++mi) {
                    MMA_F16(acc[mi][2 * p + 0], a[mi], b0, b2);
                    MMA_F16(acc[mi][2 * p + 1], a[mi], b1, b3);
                }
            }
        }
        stage = stage + 1 == NSTG ? 0 : stage + 1;
    }

    // ---------------- Epilogue ----------------
    int r = lane >> 2, c = lane & 3;
    if (MODE == 0) {
#pragma unroll
        for (int mi = 0; mi < 2; ++mi) {
#pragma unroll
            for (int hh = 0; hh < 2; ++hh) {
                int m = mt * 128 + wm * 32 + mi * 16 + hh * 8 + r;
                __half* hrow = g_h + (size_t)m * DFFN;
#pragma unroll
                for (int ni = 0; ni < 8; ++ni) {
                    int n = nt * 128 + wn * 64 + ni * 8 + c * 2;
                    float v0 = gelu_fast(acc[mi][ni][hh * 2 + 0] + bias[n]);
                    float v1 = gelu_fast(acc[mi][ni][hh * 2 + 1] + bias[n + 1]);
                    __half2 hv = __floats2half2_rn(v0, v1);
                    *reinterpret_cast<__half2*>(hrow + n) = hv;
                }
            }
        }
    } else {
        int q = blockIdx.x & 3;
        float* slot = g_part + ((size_t)tile * NQ + q) * 16384;
        // every quarter writes its fp32 partial
#pragma unroll
        for (int mi = 0; mi < 2; ++mi)
#pragma unroll
            for (int hh = 0; hh < 2; ++hh) {
                int ml = wm * 32 + mi * 16 + hh * 8 + r;
#pragma unroll
                for (int ni = 0; ni < 8; ++ni) {
                    int nl = wn * 64 + ni * 8 + c * 2;
                    float2 v = make_float2(acc[mi][ni][hh * 2], acc[mi][ni][hh * 2 + 1]);
                    *reinterpret_cast<float2*>(slot + ml * 128 + nl) = v;
                }
            }
        __threadfence();
        __syncthreads();
        if (tid == 0) sh_ticket = atomicAdd(&g_cnt[tile], 1);
        __syncthreads();
        if (sh_ticket == NQ - 1) {                 // last arriver combines
            __threadfence();
            const float* base0 = g_part + (size_t)tile * NQ * 16384;
#pragma unroll
            for (int mi = 0; mi < 2; ++mi)
#pragma unroll
                for (int hh = 0; hh < 2; ++hh) {
                    int ml = wm * 32 + mi * 16 + hh * 8 + r;
                    int m = mt * 128 + ml;
                    int tok = g_sel[m];
                    size_t obase = ((size_t)(m >> 11) * NN + tok) * DD;
#pragma unroll
                    for (int ni = 0; ni < 8; ++ni) {
                        int nl = wn * 64 + ni * 8 + c * 2;
                        int n = nt * 128 + nl;
                        float sx = acc[mi][ni][hh * 2 + 0];
                        float sy = acc[mi][ni][hh * 2 + 1];
#pragma unroll
                        for (int oq = 0; oq < NQ; ++oq) {
                            if (oq == q) continue;
                            float2 p = __ldcg(reinterpret_cast<const float2*>(
                                base0 + (size_t)oq * 16384 + ml * 128 + nl));
                            sx += p.x; sy += p.y;
                        }
                        float2 xv = *reinterpret_cast<const float2*>(xin + obase + n);
                        float2 w;
                        w.x = xv.x + sx + bias[n];
                        w.y = xv.y + sy + bias[n + 1];
                        *reinterpret_cast<float2*>(outp + obase + n) = w;
                    }
                }
        }
    }
}

// ---------------------------------------------------------------------------
// Launch: x, gate_w, w1, b1, w2, b2, k
// ---------------------------------------------------------------------------
extern "C" void kernel_launch(void* const* d_in, const int* in_sizes, int n_in,
                              void* d_out, int out_size) {
    const float* x  = (const float*)d_in[0];
    const float* gw = (const float*)d_in[1];
    const float* w1 = (const float*)d_in[2];
    const float* b1 = (const float*)d_in[3];
    const float* w2 = (const float*)d_in[4];
    const float* b2 = (const float*)d_in[5];
    float* out = (float*)d_out;

    cudaFuncSetAttribute(mma_gemm<0>, cudaFuncAttributeMaxDynamicSharedMemorySize, GSMEM_SZ);
    cudaFuncSetAttribute(mma_gemm<1>, cudaFuncAttributeMaxDynamicSharedMemorySize, GSMEM_SZ);

    // 1) gate scores (+ zero ALL split-K tickets — replay-safe)
    scores_kernel<<<(BB * NN) / 8, 256>>>(x, gw);
    // 2) topk + complement (4 CTAs) || w1^T || w2^T — one launch
    mid_kernel<<<4 + 1024 + 1024, 1024, MID_SMEM>>>(w1, w2);
    // 3) gather selected -> fp16 A || copy non-selected x -> out
    gather_copy_kernel<<<2 * MM, 256>>>(x, out);
    // 4) GEMM1: g_a[8192,1024] @ w1 -> g_h[8192,4096]  (gelu fused, fp16 out)
    mma_gemm<0><<<dim3(DFFN / 128, MM / 128), 256, GSMEM_SZ>>>(b1, nullptr, nullptr);
    // 5) GEMM2 uniform 4-way split-K: g_h @ w2 + residual -> scattered into out
    mma_gemm<1><<<N_TILES2 * NQ, 256, GSMEM_SZ>>>(b2, x, out);
}

// round 17
// speedup vs baseline: 1.0419x; 1.0419x over previous
#include <cuda_runtime.h>
#include <cuda_fp16.h>
#include <cstdint>
#include <math.h>

// Problem constants (MoDRouter_48387101556956: fixed shapes)
#define BB   4
#define NN   4096
#define DD   1024
#define DFFN 4096
#define KK   2048
#define MM   (BB * KK)   // 8192 selected tokens total

// GEMM2 mixed N-split: 512 tiles = 136 whole(128x128) + 376 pairs of 128x64
// -> 888 CTAs = 3 x 296 slots. Short tiles have NO split-K overhead: each
// writes its own N-slice directly (no partials, no tickets, no combine).
#define N_WHOLE    136

// ---------------------------------------------------------------------------
// Device scratch
// ---------------------------------------------------------------------------
__device__ float  g_scores[BB * NN];
__device__ int    g_sel[MM];                       // selected token idx per (b,j)
__device__ int    g_unsel[MM];                     // complement token idx per (b,j)
__device__ __half g_a[(size_t)MM * DD];            // gathered fp16 A (16 MB)
__device__ __half g_w1t[(size_t)DFFN * DD];        // w1^T (n-major, K contig), fp16
__device__ __half g_w2t[(size_t)DD * DFFN];        // w2^T (n-major, K contig), fp16
__device__ __half g_h[(size_t)MM * DFFN];          // gelu(x@w1+b1), fp16 (64 MB)

// ---------------------------------------------------------------------------
// Helpers
// ---------------------------------------------------------------------------
__device__ __forceinline__ uint32_t smem_u32(const void* p) {
    uint32_t a;
    asm("{ .reg .u64 t; cvta.to.shared.u64 t, %1; cvt.u32.u64 %0, t; }" : "=r"(a) : "l"(p));
    return a;
}
// gelu-tanh with HW MUFU tanh (sm_75+): |err| <= ~2^-11, inside error budget
__device__ __forceinline__ float gelu_fast(float u) {
    float arg = 0.7978845608028654f * (u + 0.044715f * u * u * u);
    float t;
    asm("tanh.approx.f32 %0, %1;" : "=f"(t) : "f"(arg));
    return 0.5f * u * (1.0f + t);
}

#define CP_ASYNC16(dst, src) \
    asm volatile("cp.async.cg.shared.global [%0], [%1], 16;" :: "r"(dst), "l"(src) : "memory")
#define CP_COMMIT() asm volatile("cp.async.commit_group;" ::: "memory")
#define CP_WAIT1()  asm volatile("cp.async.wait_group 1;" ::: "memory")

// m16n8k16 row.col fp16 MMA, fp32 accumulate (base-ISA, legal on sm_103)
#define MMA_F16(c, a, b0, b1)                                                         \
    asm volatile("mma.sync.aligned.m16n8k16.row.col.f32.f16.f16.f32 "                 \
                 "{%0,%1,%2,%3}, {%4,%5,%6,%7}, {%8,%9}, {%0,%1,%2,%3};"              \
                 : "+f"((c)[0]), "+f"((c)[1]), "+f"((c)[2]), "+f"((c)[3])             \
                 : "r"((a)[0]), "r"((a)[1]), "r"((a)[2]), "r"((a)[3]), "r"(b0), "r"(b1))

// ldmatrix 4x m8n8 b16 (non-transposed)
#define LDSM_X4(r0, r1, r2, r3, addr)                                                 \
    asm volatile("ldmatrix.sync.aligned.m8n8.x4.shared.b16 {%0,%1,%2,%3}, [%4];"      \
                 : "=r"(r0), "=r"(r1), "=r"(r2), "=r"(r3) : "r"(addr))

// ---------------------------------------------------------------------------
// 1) Gate scores — one warp per row
// ---------------------------------------------------------------------------
__global__ void scores_kernel(const float* __restrict__ x,
                              const float* __restrict__ gw) {
    int gwarp = (blockIdx.x * blockDim.x + threadIdx.x) >> 5;
    int lane  = threadIdx.x & 31;
    if (gwarp >= BB * NN) return;
    const float4* xr = reinterpret_cast<const float4*>(x + (size_t)gwarp * DD);
    const float4* g4 = reinterpret_cast<const float4*>(gw);
    float s = 0.0f;
#pragma unroll
    for (int i = 0; i < DD / 4 / 32; ++i) {
        float4 a = xr[lane + i * 32];
        float4 b = g4[lane + i * 32];
        s += a.x * b.x + a.y * b.y + a.z * b.z + a.w * b.w;
    }
#pragma unroll
    for (int o = 16; o; o >>= 1) s += __shfl_xor_sync(0xFFFFFFFFu, s, o);
    if (lane == 0) g_scores[gwarp] = s;
}

// ---------------------------------------------------------------------------
// 2) MID kernel: CTAs 0-3 run per-batch exact top-K (radix select) AND build
//    the complement list; CTAs 4..2051 transpose w1/w2 to fp16 K-major.
// ---------------------------------------------------------------------------
#define MID_SMEM 33824   // keys 16K | eqidx/flags 16K | hist 1K | ctrl 32B

__global__ void mid_kernel(const float* __restrict__ w1,
                           const float* __restrict__ w2) {
    extern __shared__ char sh[];
    int bid = blockIdx.x, tid = threadIdx.x, nthr = blockDim.x;

    if (bid >= 4) {
        // ---- transpose path: 4 subtiles of 32x32 per CTA ----
        float (*t)[32][33] = reinterpret_cast<float (*)[32][33]>(sh);
        int sub  = tid >> 8;
        int stid = tid & 255;
        int tx = stid & 31, ty = stid >> 5;
        const float* src; __half* dst; int R, C, bx, by;
        if (bid < 4 + 1024) {
            int r = (bid - 4) * 4 + sub;
            src = w1; dst = g_w1t; R = DD; C = DFFN;
            bx = (r & 127) * 32; by = (r >> 7) * 32;
        } else {
            int r = (bid - 4 - 1024) * 4 + sub;
            src = w2; dst = g_w2t; R = DFFN; C = DD;
            bx = (r & 31) * 32; by = (r >> 5) * 32;
        }
#pragma unroll
        for (int i = 0; i < 32; i += 8)
            t[sub][ty + i][tx] = src[(size_t)(by + ty + i) * C + bx + tx];
        __syncthreads();
#pragma unroll
        for (int i = 0; i < 32; i += 8)
            dst[(size_t)(bx + ty + i) * R + by + tx] = __float2half_rn(t[sub][tx][ty + i]);
        return;
    }

    // ---- top-K path (CTAs 0-3, one batch each) ----
    uint32_t* keys  = reinterpret_cast<uint32_t*>(sh);
    int*      eqidx = reinterpret_cast<int*>(sh + 16384);
    int*      hist  = reinterpret_cast<int*>(sh + 32768);
    int*      ctrl  = reinterpret_cast<int*>(sh + 33792);
    int b = bid;

    for (int i = tid; i < NN; i += nthr) {
        uint32_t u = __float_as_uint(g_scores[b * NN + i]);
        u = (u & 0x80000000u) ? ~u : (u | 0x80000000u);   // monotone map
        keys[i] = u;
    }
    if (tid == 0) { ctrl[1] = KK; ctrl[2] = 0; ctrl[4] = 0; }
    __syncthreads();

    for (int byte = 3; byte >= 0; --byte) {
        if (tid < 256) hist[tid] = 0;
        __syncthreads();
        int shift = byte * 8;
        uint32_t pfx = (uint32_t)ctrl[4];
        for (int i = tid; i < NN; i += nthr) {
            uint32_t u = keys[i];
            bool active = (byte == 3) || ((u >> (shift + 8)) == pfx);
            if (active) atomicAdd(&hist[(u >> shift) & 0xFF], 1);
        }
        __syncthreads();
        if (tid == 0) {
            int R = ctrl[1], cum = 0, v = 255;
            for (; v > 0; --v) {
                if (cum + hist[v] >= R) break;
                cum += hist[v];
            }
            ctrl[0] = v;
            ctrl[1] = R - cum;
            ctrl[4] = (int)((pfx << 8) | (uint32_t)v);
        }
        __syncthreads();
        int bnd = ctrl[0];
        for (int i = tid; i < NN; i += nthr) {
            uint32_t u = keys[i];
            bool active = (byte == 3) || ((u >> (shift + 8)) == pfx);
            if (active && (int)((u >> shift) & 0xFF) > bnd) {
                int slot = atomicAdd(&ctrl[2], 1);
                g_sel[b * KK + slot] = i;
            }
        }
        __syncthreads();
    }

    // Exact tie handling at the threshold key: smallest indices win (jax rule)
    if (tid == 0) ctrl[3] = 0;
    __syncthreads();
    uint32_t T = (uint32_t)ctrl[4];
    for (int i = tid; i < NN; i += nthr)
        if (keys[i] == T) eqidx[atomicAdd(&ctrl[3], 1)] = i;
    __syncthreads();
    int R = ctrl[1], en = ctrl[3];
    for (int j = tid; j < en; j += nthr) {
        int idx = eqidx[j], rank = 0;
        for (int t2 = 0; t2 < en; ++t2) rank += (eqidx[t2] < idx);
        if (rank < R) {
            int slot = atomicAdd(&ctrl[2], 1);
            g_sel[b * KK + slot] = idx;
        }
    }

    // ---- complement list: flags from g_sel (just written by THIS CTA) ----
    __syncthreads();
    int* flags = eqidx;                         // reuse 16KB as 4096 int flags
    for (int i = tid; i < NN; i += nthr) flags[i] = 0;
    if (tid == 0) ctrl[5] = 0;
    __syncthreads();
    for (int j = tid; j < KK; j += nthr) flags[g_sel[b * KK + j]] = 1;
    __syncthreads();
    for (int i = tid; i < NN; i += nthr)
        if (!flags[i]) {
            int slot = atomicAdd(&ctrl[5], 1);
            g_unsel[b * KK + slot] = i;
        }
}

// ---------------------------------------------------------------------------
// 3) Gather selected rows -> fp16 g_a  ||  copy non-selected rows x -> out
// ---------------------------------------------------------------------------
__global__ void gather_copy_kernel(const float* __restrict__ x,
                                   float* __restrict__ out) {
    int bid = blockIdx.x, c = threadIdx.x;
    if (bid < MM) {
        int tok = g_sel[bid];
        size_t src = ((size_t)(bid >> 11) * NN + tok) * DD + c * 4;
        float4 v = *reinterpret_cast<const float4*>(x + src);
        __half2 h0 = __floats2half2_rn(v.x, v.y);
        __half2 h1 = __floats2half2_rn(v.z, v.w);
        uint2 pk;
        pk.x = *reinterpret_cast<uint32_t*>(&h0);
        pk.y = *reinterpret_cast<uint32_t*>(&h1);
        *reinterpret_cast<uint2*>(g_a + (size_t)bid * DD + c * 4) = pk;
    } else {
        int m2 = bid - MM;
        int tok = g_unsel[m2];
        size_t base = ((size_t)(m2 >> 11) * NN + tok) * DD + c * 4;
        *reinterpret_cast<float4*>(out + base) =
            *reinterpret_cast<const float4*>(x + base);
    }
}

// ---------------------------------------------------------------------------
// fp16 mma.sync GEMM core, templated on N-tile width NT (128 or 64).
// CTA: 256 thr, 8 warps 4(M) x 2(N); warp tile 32 x NT/2.
// BK=64, 3-stage cp.async pipeline, ONE __syncthreads per K-iter.
// Row pitch 144B keeps ldmatrix phases conflict-free.
//   MODE 0 (NT=128): g_h = h(gelu(g_a @ w1t^T + b1)),  K=1024
//   MODE 1 (NT=128|64): out[sel] = x[sel] + g_h @ w2t^T + b2,  K=4096
// ---------------------------------------------------------------------------
#define HPITCH_B 144                               // bytes per row (72 halves)
#define A_STG (128 * HPITCH_B)
#define B_STG (128 * HPITCH_B)                     // sized for NT=128; NT=64 uses half
#define NSTG 3
#define GSMEM_SZ (NSTG * (A_STG + B_STG))          // 110592 B per CTA

template <int NT>
__device__ __forceinline__ void ld_stage(uint32_t sb, int stage,
                                         const __half* __restrict__ A,
                                         const __half* __restrict__ Bw,
                                         int Kdim, int mt, int n0, int k0, int tid) {
    uint32_t abase = sb + stage * A_STG;
    uint32_t bbase = sb + NSTG * A_STG + stage * B_STG;
#pragma unroll
    for (int i = 0; i < 4; ++i) {                  // A: 128 rows x 8 chunks
        int lin = i * 256 + tid;
        int row = lin >> 3, ch = lin & 7;
        CP_ASYNC16(abase + row * HPITCH_B + ch * 16,
                   A + (size_t)(mt * 128 + row) * Kdim + k0 + ch * 8);
    }
#pragma unroll
    for (int i = 0; i < NT / 32; ++i) {            // B: NT rows x 8 chunks
        int lin = i * 256 + tid;
        int row = lin >> 3, ch = lin & 7;
        CP_ASYNC16(bbase + row * HPITCH_B + ch * 16,
                   Bw + (size_t)(n0 + row) * Kdim + k0 + ch * 8);
    }
}

template <int MODE, int NT>
__device__ __forceinline__ void gemm_core(uint32_t sb, int tid, int mt, int n0,
                                          int KT,
                                          const float* __restrict__ bias,
                                          const float* __restrict__ xin,
                                          float* __restrict__ outp) {
    const __half* A    = (MODE == 0) ? g_a   : g_h;
    const __half* Bw   = (MODE == 0) ? g_w1t : g_w2t;
    const int     Kdim = (MODE == 0) ? DD : DFFN;
    constexpr int WN   = NT / 2;                   // warp N extent
    constexpr int PMAX = NT / 32;                  // ldsm B groups per warp
    constexpr int NI   = NT / 16;                  // mma n-tiles per warp

    int lane = tid & 31, wid = tid >> 5;
    int wm = wid >> 1, wn = wid & 1;

    int lrow = ((lane >> 3) & 1) * 8 + (lane & 7);
    int koff = (lane >= 16) ? 16 : 0;
    uint32_t a_off[2], b_off[PMAX];
#pragma unroll
    for (int mi = 0; mi < 2; ++mi)
        a_off[mi] = (wm * 32 + mi * 16 + lrow) * HPITCH_B + koff;
#pragma unroll
    for (int p = 0; p < PMAX; ++p)
        b_off[p] = (wn * WN + p * 16 + lrow) * HPITCH_B + koff;

    float acc[2][NI][4];
#pragma unroll
    for (int mi = 0; mi < 2; ++mi)
#pragma unroll
        for (int ni = 0; ni < NI; ++ni)
#pragma unroll
            for (int q = 0; q < 4; ++q) acc[mi][ni][q] = 0.0f;

    ld_stage<NT>(sb, 0, A, Bw, Kdim, mt, n0, 0, tid);
    CP_COMMIT();
    ld_stage<NT>(sb, 1, A, Bw, Kdim, mt, n0, 64, tid);
    CP_COMMIT();

    int stage = 0;
    for (int k = 0; k < KT; ++k) {
        CP_WAIT1();
        __syncthreads();

        int pstage = stage + 2 >= NSTG ? stage + 2 - NSTG : stage + 2;
        if (k + 2 < KT)
            ld_stage<NT>(sb, pstage, A, Bw, Kdim, mt, n0, (k + 2) * 64, tid);
        CP_COMMIT();

        uint32_t As_addr = sb + stage * A_STG;
        uint32_t Bs_addr = sb + NSTG * A_STG + stage * B_STG;
#pragma unroll
        for (int ks = 0; ks < 4; ++ks) {           // 4 x K=16
            uint32_t a[2][4];
#pragma unroll
            for (int mi = 0; mi < 2; ++mi)
                LDSM_X4(a[mi][0], a[mi][1], a[mi][2], a[mi][3],
                        As_addr + a_off[mi] + ks * 32);
#pragma unroll
            for (int p = 0; p < PMAX; ++p) {
                uint32_t b0, b1, b2, b3;           // (ni0.k0, ni1.k0, ni0.k8, ni1.k8)
                LDSM_X4(b0, b1, b2, b3, Bs_addr + b_off[p] + ks * 32);
#pragma unroll
                for (int mi = 0; mi < 2; ++mi) {
                    MMA_F16(acc[mi][2 * p + 0], a[mi], b0, b2);
                    MMA_F16(acc[mi][2 * p + 1], a[mi], b1, b3);
                }
            }
        }
        stage = stage + 1 == NSTG ? 0 : stage + 1;
    }

    // ---------------- Epilogue (direct, no partials) ----------------
    int r = lane >> 2, c = lane & 3;
    if (MODE == 0) {
#pragma unroll
        for (int mi = 0; mi < 2; ++mi) {
#pragma unroll
            for (int hh = 0; hh < 2; ++hh) {
                int m = mt * 128 + wm * 32 + mi * 16 + hh * 8 + r;
                __half* hrow = g_h + (size_t)m * DFFN;
#pragma unroll
                for (int ni = 0; ni < NI; ++ni) {
                    int n = n0 + wn * WN + ni * 8 + c * 2;
                    float v0 = gelu_fast(acc[mi][ni][hh * 2 + 0] + bias[n]);
                    float v1 = gelu_fast(acc[mi][ni][hh * 2 + 1] + bias[n + 1]);
                    __half2 hv = __floats2half2_rn(v0, v1);
                    *reinterpret_cast<__half2*>(hrow + n) = hv;
                }
            }
        }
    } else {
#pragma unroll
        for (int mi = 0; mi < 2; ++mi) {
#pragma unroll
            for (int hh = 0; hh < 2; ++hh) {
                int m = mt * 128 + wm * 32 + mi * 16 + hh * 8 + r;
                int tok = g_sel[m];
                size_t base = ((size_t)(m >> 11) * NN + tok) * DD;
#pragma unroll
                for (int ni = 0; ni < NI; ++ni) {
                    int n = n0 + wn * WN + ni * 8 + c * 2;
                    float2 xv = *reinterpret_cast<const float2*>(xin + base + n);
                    float2 w;
                    w.x = xv.x + acc[mi][ni][hh * 2 + 0] + bias[n];
                    w.y = xv.y + acc[mi][ni][hh * 2 + 1] + bias[n + 1];
                    *reinterpret_cast<float2*>(outp + base + n) = w;
                }
            }
        }
    }
}

// GEMM1: uniform 128x128 tiles, K=1024 (16 iters)
__global__ __launch_bounds__(256, 2)
void mma_gemm1(const float* __restrict__ bias) {
    extern __shared__ uint32_t smw[];
    uint32_t sb = smem_u32(smw);
    gemm_core<0, 128>(sb, threadIdx.x, blockIdx.y, blockIdx.x * 128, DD / 64,
                      bias, nullptr, nullptr);
}

// GEMM2: mixed 128x128 / 128x64 tiles, K=4096 (64 iters), direct epilogues
__global__ __launch_bounds__(256, 2)
void mma_gemm2(const float* __restrict__ bias,
               const float* __restrict__ xin,
               float* __restrict__ outp) {
    extern __shared__ uint32_t smw[];
    uint32_t sb = smem_u32(smw);
    int bid = blockIdx.x;
    if (bid < N_WHOLE) {
        int tile = bid;
        gemm_core<1, 128>(sb, threadIdx.x, tile >> 3, (tile & 7) * 128,
                          DFFN / 64, bias, xin, outp);
    } else {
        int i = bid - N_WHOLE;
        int tile = N_WHOLE + (i >> 1);
        int nh = i & 1;
        gemm_core<1, 64>(sb, threadIdx.x, tile >> 3, (tile & 7) * 128 + nh * 64,
                         DFFN / 64, bias, xin, outp);
    }
}

// ---------------------------------------------------------------------------
// Launch: x, gate_w, w1, b1, w2, b2, k
// ---------------------------------------------------------------------------
extern "C" void kernel_launch(void* const* d_in, const int* in_sizes, int n_in,
                              void* d_out, int out_size) {
    const float* x  = (const float*)d_in[0];
    const float* gw = (const float*)d_in[1];
    const float* w1 = (const float*)d_in[2];
    const float* b1 = (const float*)d_in[3];
    const float* w2 = (const float*)d_in[4];
    const float* b2 = (const float*)d_in[5];
    float* out = (float*)d_out;

    cudaFuncSetAttribute(mma_gemm1, cudaFuncAttributeMaxDynamicSharedMemorySize, GSMEM_SZ);
    cudaFuncSetAttribute(mma_gemm2, cudaFuncAttributeMaxDynamicSharedMemorySize, GSMEM_SZ);

    // 1) gate scores
    scores_kernel<<<(BB * NN) / 8, 256>>>(x, gw);
    // 2) topk + complement (4 CTAs) || w1^T || w2^T — one launch
    mid_kernel<<<4 + 1024 + 1024, 1024, MID_SMEM>>>(w1, w2);
    // 3) gather selected -> fp16 A || copy non-selected x -> out
    gather_copy_kernel<<<2 * MM, 256>>>(x, out);
    // 4) GEMM1: g_a[8192,1024] @ w1 -> g_h[8192,4096]  (gelu fused, fp16 out)
    mma_gemm1<<<dim3(DFFN / 128, MM / 128), 256, GSMEM_SZ>>>(b1);
    // 5) GEMM2 mixed N-split (888 CTAs = 3 waves): residual + scatter into out
    mma_gemm2<<<N_WHOLE + 2 * (512 - N_WHOLE), 256, GSMEM_SZ>>>(b2, x, out);
}